// round 2
// baseline (speedup 1.0000x reference)
#include <cuda_runtime.h>
#include <math.h>

#define BVAL 32
#define TVAL 32
#define SVAL 128
#define HVAL 512
#define EVAL 512
#define VVAL 50257
#define LVAL 2
#define SOS_ID 1

// ---------------- scratch (device globals; no runtime allocation) ----------------
__device__ float g_encproj[SVAL * BVAL * HVAL];        // (s*B+b, H)  = enc @ Wa^T + ba
__device__ float g_xall[TVAL * BVAL * EVAL];           // (t*B+b, E)  embedded inputs
__device__ float g_gx0[TVAL * BVAL * 3 * HVAL];        // (t*B+b, 3H) layer-0 input gates
__device__ float g_hbuf[2][LVAL * BVAL * HVAL];        // ping-pong hidden state
__device__ float g_ctx[BVAL * HVAL];                   // attention context per step
__device__ float g_concats[TVAL * BVAL * HVAL];        // (t*B+b, H)

// ---------------- small copy kernels ----------------
__global__ void init_h_kernel(const float* __restrict__ dh) {
    int i = blockIdx.x * blockDim.x + threadIdx.x;
    if (i < LVAL * BVAL * HVAL) g_hbuf[0][i] = dh[i];
}

__global__ void final_h_kernel(float* __restrict__ out) {
    int i = blockIdx.x * blockDim.x + threadIdx.x;
    if (i < LVAL * BVAL * HVAL) out[i] = g_hbuf[0][i];
}

// ---------------- embedding gather for all timesteps ----------------
__global__ void embed_kernel(const int* __restrict__ tgt, const float* __restrict__ emb) {
    int row = blockIdx.x;           // t*B + b
    int t = row >> 5, b = row & 31;
    int tok = (t == 0) ? SOS_ID : tgt[b * TVAL + t - 1];
    float4 v = *(const float4*)(emb + (size_t)tok * EVAL + threadIdx.x * 4);
    *(float4*)(g_xall + (size_t)row * EVAL + threadIdx.x * 4) = v;
}

// ---------------- tiled SGEMM:  C[M,N] = A[M,K] @ B[N,K]^T + bias[N] ----------------
// BM=BN=128, BK=8, 256 threads, 8x8 micro-tile, warp tile 32x64.
// a_sel: 0=param, 1=g_xall, 2=g_concats ; c_sel: 0=param, 1=g_encproj, 2=g_gx0
__global__ __launch_bounds__(256) void sgemm_bias_kernel(
    const float* __restrict__ Ap, const float* __restrict__ Bw,
    const float* __restrict__ bias, float* __restrict__ Cp,
    int M, int N, int K, int a_sel, int c_sel)
{
    const float* A = (a_sel == 0) ? Ap : (a_sel == 1) ? g_xall : g_concats;
    float* C = (c_sel == 0) ? Cp : (c_sel == 1) ? g_encproj : g_gx0;

    __shared__ float As[8][132];
    __shared__ float Bs[8][132];

    const int tid = threadIdx.x;
    const int m0 = blockIdx.y * 128;
    const int n0 = blockIdx.x * 128;
    const int warp = tid >> 5, lane = tid & 31;
    const int wm = (warp & 3) * 32;
    const int wn = (warp >> 2) * 64;
    const int tm = wm + (lane >> 3) * 4;
    const int tn = wn + (lane & 7) * 4;

    float acc[8][8];
#pragma unroll
    for (int i = 0; i < 8; i++)
#pragma unroll
        for (int j = 0; j < 8; j++) acc[i][j] = 0.f;

    const int lrow = tid >> 1;
    const int lcol = (tid & 1) * 4;
    const float* Ald = A + (size_t)(m0 + lrow) * K + lcol;
    const int gn = n0 + lrow;
    const bool bvalid = gn < N;
    const float* Bld = Bw + (size_t)(bvalid ? gn : 0) * K + lcol;

    for (int k0 = 0; k0 < K; k0 += 8) {
        float4 av = *(const float4*)(Ald + k0);
        float4 bv = make_float4(0.f, 0.f, 0.f, 0.f);
        if (bvalid) bv = *(const float4*)(Bld + k0);
        As[lcol + 0][lrow] = av.x; As[lcol + 1][lrow] = av.y;
        As[lcol + 2][lrow] = av.z; As[lcol + 3][lrow] = av.w;
        Bs[lcol + 0][lrow] = bv.x; Bs[lcol + 1][lrow] = bv.y;
        Bs[lcol + 2][lrow] = bv.z; Bs[lcol + 3][lrow] = bv.w;
        __syncthreads();
#pragma unroll
        for (int k = 0; k < 8; k++) {
            float4 a0 = *(const float4*)&As[k][tm];
            float4 a1 = *(const float4*)&As[k][tm + 16];
            float4 b0 = *(const float4*)&Bs[k][tn];
            float4 b1 = *(const float4*)&Bs[k][tn + 32];
            float a[8] = {a0.x, a0.y, a0.z, a0.w, a1.x, a1.y, a1.z, a1.w};
            float b[8] = {b0.x, b0.y, b0.z, b0.w, b1.x, b1.y, b1.z, b1.w};
#pragma unroll
            for (int i = 0; i < 8; i++)
#pragma unroll
                for (int j = 0; j < 8; j++)
                    acc[i][j] = fmaf(a[i], b[j], acc[i][j]);
        }
        __syncthreads();
    }
#pragma unroll
    for (int i = 0; i < 8; i++) {
        int gm = m0 + tm + ((i < 4) ? i : (12 + i));
        float* crow = C + (size_t)gm * N;
#pragma unroll
        for (int j = 0; j < 8; j++) {
            int gc = n0 + tn + ((j < 4) ? j : (28 + j));
            if (gc < N) crow[gc] = acc[i][j] + bias[gc];
        }
    }
}

// ---------------- fused GRU step (one layer) ----------------
// HAS_X=false: layer 0, input-gate part precomputed in g_gx0 (selected via t)
// HAS_X=true : layer 1, x = freshly written layer-0 hidden in g_hbuf[buf_out]
// warp = one output column j (4 per block, 128 blocks), lanes = batch.
template <bool HAS_X>
__global__ __launch_bounds__(128) void gru_step_kernel(
    const float* __restrict__ Wih, const float* __restrict__ Whh,
    const float* __restrict__ bih, const float* __restrict__ bhh,
    int t, int layer, int buf_in, int buf_out)
{
    constexpr int PER = HAS_X ? 6 : 3;
    __shared__ float h_s[32][133];
    __shared__ float x_s[HAS_X ? 32 : 1][133];
    __shared__ float w_s[PER * 4][128];

    const int tid = threadIdx.x;
    const int warp = tid >> 5, lane = tid & 31;
    const int j = blockIdx.x * 4 + warp;
    const int b = lane;

    const float* h_in = g_hbuf[buf_in] + layer * BVAL * HVAL;
    const float* x_in = g_hbuf[buf_out];            // layer-0 new hidden (only if HAS_X)
    float* h_out = g_hbuf[buf_out] + layer * BVAL * HVAL;

    float ar = 0.f, az = 0.f, an = 0.f;             // h-side gates
    float xr = 0.f, xz = 0.f, xn = 0.f;             // x-side gates (HAS_X)

    for (int k0 = 0; k0 < HVAL; k0 += 128) {
        // stage h (and x) tile: 32 x 128 floats, coalesced float4 loads
#pragma unroll
        for (int it = 0; it < 8; ++it) {
            int flat = tid + it * 128;
            int bb = flat >> 5, kq = flat & 31;
            float4 v = *(const float4*)(h_in + bb * HVAL + k0 + kq * 4);
            h_s[bb][kq * 4 + 0] = v.x; h_s[bb][kq * 4 + 1] = v.y;
            h_s[bb][kq * 4 + 2] = v.z; h_s[bb][kq * 4 + 3] = v.w;
            if (HAS_X) {
                float4 u = *(const float4*)(x_in + bb * HVAL + k0 + kq * 4);
                x_s[bb][kq * 4 + 0] = u.x; x_s[bb][kq * 4 + 1] = u.y;
                x_s[bb][kq * 4 + 2] = u.z; x_s[bb][kq * 4 + 3] = u.w;
            }
        }
        // stage weight rows: PER rows per j, 4 j per block
#pragma unroll
        for (int it = 0; it < PER; ++it) {
            int flat = tid + it * 128;
            int r = flat >> 5, kq = flat & 31;
            int jl = r / PER, which = r % PER;
            int jj = blockIdx.x * 4 + jl;
            const float* src;
            if (HAS_X)
                src = (which < 3) ? (Wih + ((size_t)(which * HVAL + jj)) * HVAL)
                                  : (Whh + ((size_t)((which - 3) * HVAL + jj)) * HVAL);
            else
                src = Whh + ((size_t)(which * HVAL + jj)) * HVAL;
            float4 w = *(const float4*)(src + k0 + kq * 4);
            w_s[r][kq * 4 + 0] = w.x; w_s[r][kq * 4 + 1] = w.y;
            w_s[r][kq * 4 + 2] = w.z; w_s[r][kq * 4 + 3] = w.w;
        }
        __syncthreads();
        const int wb = warp * PER;
#pragma unroll 4
        for (int k = 0; k < 128; k++) {
            float hv = h_s[b][k];
            if (HAS_X) {
                float xv = x_s[b][k];
                xr = fmaf(w_s[wb + 0][k], xv, xr);
                xz = fmaf(w_s[wb + 1][k], xv, xz);
                xn = fmaf(w_s[wb + 2][k], xv, xn);
                ar = fmaf(w_s[wb + 3][k], hv, ar);
                az = fmaf(w_s[wb + 4][k], hv, az);
                an = fmaf(w_s[wb + 5][k], hv, an);
            } else {
                ar = fmaf(w_s[wb + 0][k], hv, ar);
                az = fmaf(w_s[wb + 1][k], hv, az);
                an = fmaf(w_s[wb + 2][k], hv, an);
            }
        }
        __syncthreads();
    }

    float gxr, gxz, gxn;
    if (HAS_X) {
        gxr = xr + bih[j]; gxz = xz + bih[HVAL + j]; gxn = xn + bih[2 * HVAL + j];
    } else {
        const float* g = g_gx0 + ((size_t)(t * BVAL + b)) * 3 * HVAL;
        gxr = g[j]; gxz = g[HVAL + j]; gxn = g[2 * HVAL + j];
    }
    float ghr = ar + bhh[j];
    float ghz = az + bhh[HVAL + j];
    float ghn = an + bhh[2 * HVAL + j];
    float rg = 1.f / (1.f + __expf(-(gxr + ghr)));
    float zg = 1.f / (1.f + __expf(-(gxz + ghz)));
    float ng = tanhf(gxn + rg * ghn);
    h_out[b * HVAL + j] = (1.f - zg) * ng + zg * h_in[b * HVAL + j];
}

// ---------------- attention: scores -> softmax -> context ----------------
__global__ __launch_bounds__(128) void attn_kernel(
    const float* __restrict__ enc,            // (S*B, H) row s*B+b
    const unsigned char* __restrict__ mask,   // (B, S) bool
    int hb)
{
    const int b = blockIdx.x;
    const int tid = threadIdx.x;
    const int warp = tid >> 5, lane = tid & 31;
    const float* h1 = g_hbuf[hb] + BVAL * HVAL;   // layer-1 new hidden

    __shared__ float hs[HVAL];
    __shared__ float sc[SVAL];
    __shared__ float red[4];

    ((float4*)hs)[tid] = *(const float4*)(h1 + b * HVAL + tid * 4);
    __syncthreads();

    // scores[s] = <h1[b], encproj[s*B+b]>
    for (int s = warp; s < SVAL; s += 4) {
        const float* ep = g_encproj + ((size_t)(s * BVAL + b)) * HVAL;
        float p = 0.f;
#pragma unroll 4
        for (int k = lane; k < HVAL; k += 32) p = fmaf(hs[k], ep[k], p);
#pragma unroll
        for (int o = 16; o > 0; o >>= 1) p += __shfl_down_sync(0xffffffffu, p, o);
        if (lane == 0) sc[s] = mask[b * SVAL + s] ? -1e9f : p;
    }
    __syncthreads();

    // softmax over 128 (one value per thread)
    float v = sc[tid];
    float m = v;
#pragma unroll
    for (int o = 16; o > 0; o >>= 1) m = fmaxf(m, __shfl_xor_sync(0xffffffffu, m, o));
    if (lane == 0) red[warp] = m;
    __syncthreads();
    m = fmaxf(fmaxf(red[0], red[1]), fmaxf(red[2], red[3]));
    __syncthreads();
    float e = __expf(v - m);
    float s = e;
#pragma unroll
    for (int o = 16; o > 0; o >>= 1) s += __shfl_xor_sync(0xffffffffu, s, o);
    if (lane == 0) red[warp] = s;
    __syncthreads();
    s = red[0] + red[1] + red[2] + red[3];
    sc[tid] = e / s;
    __syncthreads();

    // ctx[b,h] = sum_s p[s] * enc[s,b,h]
    for (int hh = tid; hh < HVAL; hh += 128) {
        float acc = 0.f;
#pragma unroll 4
        for (int ss = 0; ss < SVAL; ss++)
            acc = fmaf(sc[ss], enc[((size_t)(ss * BVAL + b)) * HVAL + hh], acc);
        g_ctx[b * HVAL + hh] = acc;
    }
}

// ---------------- concat projection: tanh(Wc @ [ctx; h1] + bc) ----------------
__global__ __launch_bounds__(128) void concat_kernel(
    const float* __restrict__ Wc, const float* __restrict__ bc, int t, int hb)
{
    __shared__ float c_s[32][133];
    __shared__ float w_s[4][128];
    const int tid = threadIdx.x;
    const int warp = tid >> 5, lane = tid & 31;
    const int j = blockIdx.x * 4 + warp;
    const int b = lane;
    const float* h1 = g_hbuf[hb] + BVAL * HVAL;

    float acc = 0.f;
    for (int k0 = 0; k0 < 2 * HVAL; k0 += 128) {
#pragma unroll
        for (int it = 0; it < 8; ++it) {
            int flat = tid + it * 128;
            int bb = flat >> 5, kq = flat & 31;
            int k = k0 + kq * 4;
            const float* src = (k < HVAL) ? (g_ctx + bb * HVAL + k)
                                          : (h1 + bb * HVAL + (k - HVAL));
            float4 v = *(const float4*)src;
            c_s[bb][kq * 4 + 0] = v.x; c_s[bb][kq * 4 + 1] = v.y;
            c_s[bb][kq * 4 + 2] = v.z; c_s[bb][kq * 4 + 3] = v.w;
        }
        {
            int r = tid >> 5, kq = tid & 31;
            float4 w = *(const float4*)(Wc + ((size_t)(blockIdx.x * 4 + r)) * 2 * HVAL + k0 + kq * 4);
            w_s[r][kq * 4 + 0] = w.x; w_s[r][kq * 4 + 1] = w.y;
            w_s[r][kq * 4 + 2] = w.z; w_s[r][kq * 4 + 3] = w.w;
        }
        __syncthreads();
#pragma unroll 4
        for (int k = 0; k < 128; k++)
            acc = fmaf(w_s[warp][k], c_s[b][k], acc);
        __syncthreads();
    }
    g_concats[((size_t)(t * BVAL + b)) * HVAL + j] = tanhf(acc + bc[j]);
}

// ---------------- launcher ----------------
extern "C" void kernel_launch(void* const* d_in, const int* in_sizes, int n_in,
                              void* d_out, int out_size) {
    const int* tgt            = (const int*)d_in[0];
    const float* dh           = (const float*)d_in[1];
    const float* enc          = (const float*)d_in[2];
    const unsigned char* mask = (const unsigned char*)d_in[3];
    const float* emb          = (const float*)d_in[4];
    const float* Wih          = (const float*)d_in[5];
    const float* Whh          = (const float*)d_in[6];
    const float* bih          = (const float*)d_in[7];
    const float* bhh          = (const float*)d_in[8];
    const float* Wa           = (const float*)d_in[9];
    const float* ba           = (const float*)d_in[10];
    const float* Wc           = (const float*)d_in[11];
    const float* bc           = (const float*)d_in[12];
    const float* Ws           = (const float*)d_in[13];
    const float* bs           = (const float*)d_in[14];
    float* out = (float*)d_out;

    // hidden-state init + embeddings
    init_h_kernel<<<(LVAL * BVAL * HVAL + 255) / 256, 256>>>(dh);
    embed_kernel<<<TVAL * BVAL, 128>>>(tgt, emb);

    // enc_proj = enc @ Wa^T + ba   (M=4096, N=512, K=512) -> g_encproj
    sgemm_bias_kernel<<<dim3(HVAL / 128, (SVAL * BVAL) / 128), 256>>>(
        enc, Wa, ba, nullptr, SVAL * BVAL, HVAL, HVAL, 0, 1);

    // gx0 = x_all @ Wih0^T + bih0  (M=1024, N=1536, K=512) -> g_gx0
    sgemm_bias_kernel<<<dim3(3 * HVAL / 128, (TVAL * BVAL) / 128), 256>>>(
        nullptr, Wih, bih, nullptr, TVAL * BVAL, 3 * HVAL, EVAL, 1, 2);

    // recurrence
    for (int t = 0; t < TVAL; t++) {
        int bin = t & 1, bout = (t + 1) & 1;
        gru_step_kernel<false><<<128, 128>>>(nullptr, Whh, nullptr, bhh, t, 0, bin, bout);
        gru_step_kernel<true><<<128, 128>>>(Wih + 3 * HVAL * EVAL, Whh + 3 * HVAL * HVAL,
                                            bih + 3 * HVAL, bhh + 3 * HVAL, t, 1, bin, bout);
        attn_kernel<<<BVAL, 128>>>(enc, mask, bout);
        concat_kernel<<<128, 128>>>(Wc, bc, t, bout);
    }

    // decoder_outputs = concats @ Ws^T + bs  (M=1024, N=50257, K=512)
    sgemm_bias_kernel<<<dim3((VVAL + 127) / 128, (TVAL * BVAL) / 128), 256>>>(
        nullptr, Ws, bs, out, TVAL * BVAL, VVAL, HVAL, 2, 0);

    // h_final tail
    long main_elems = (long)TVAL * BVAL * VVAL;
    if ((long)out_size >= main_elems + (long)LVAL * BVAL * HVAL)
        final_h_kernel<<<128, 256>>>(out + main_elems);
}

// round 4
// speedup vs baseline: 1.1488x; 1.1488x over previous
#include <cuda_runtime.h>
#include <cuda_bf16.h>
#include <math.h>

#define BVAL 32
#define TVAL 32
#define SVAL 128
#define HVAL 512
#define EVAL 512
#define VVAL 50257
#define LVAL 2
#define SOS_ID 1
#define KSPLIT 1536   // [hi | lo | hi] x [hi | hi | lo]

// ---------------- scratch (device globals; no runtime allocation) ----------------
__device__ float g_encproj[SVAL * BVAL * HVAL];        // (s*B+b, H)
__device__ float g_xall[TVAL * BVAL * EVAL];           // (t*B+b, E)
__device__ float g_gx0[TVAL * BVAL * 3 * HVAL];        // (t*B+b, 3H)
__device__ float g_hbuf[2][LVAL * BVAL * HVAL];        // ping-pong hidden state
__device__ float g_ctx[BVAL * HVAL];
__device__ float g_concats[TVAL * BVAL * HVAL];
__device__ __nv_bfloat16 g_Asplit[4096 * KSPLIT];      // split activations (max M=4096)
__device__ __nv_bfloat16 g_Bsplit[VVAL * KSPLIT];      // split weights (max N=V)

__device__ __forceinline__ unsigned smem_u32(const void* p) {
    unsigned a;
    asm("{ .reg .u64 t; cvta.to.shared.u64 t, %1; cvt.u32.u64 %0, t; }" : "=r"(a) : "l"(p));
    return a;
}

// swizzled smem byte offset for a (row, 16B-chunk) within a 128x32 bf16 tile
__device__ __forceinline__ unsigned swz_off(int row, int chunk) {
    return (unsigned)(row * 64 + ((chunk ^ ((row >> 1) & 3)) << 4));
}

#define LDSM4(R0,R1,R2,R3,ADDR) \
    asm volatile("ldmatrix.sync.aligned.m8n8.x4.shared.b16 {%0,%1,%2,%3}, [%4];" \
        : "=r"(R0),"=r"(R1),"=r"(R2),"=r"(R3) : "r"(ADDR))

#define MMA16816(D,A0,A1,A2,A3,B0,B1) \
    asm volatile("mma.sync.aligned.m16n8k16.row.col.f32.bf16.bf16.f32 " \
        "{%0,%1,%2,%3}, {%4,%5,%6,%7}, {%8,%9}, {%0,%1,%2,%3};" \
        : "+f"(D[0]),"+f"(D[1]),"+f"(D[2]),"+f"(D[3]) \
        : "r"(A0),"r"(A1),"r"(A2),"r"(A3),"r"(B0),"r"(B1))

// ---------------- small kernels ----------------
__global__ void init_h_kernel(const float* __restrict__ dh) {
    int i = blockIdx.x * blockDim.x + threadIdx.x;
    if (i < LVAL * BVAL * HVAL) g_hbuf[0][i] = dh[i];
}
__global__ void final_h_kernel(float* __restrict__ out) {
    int i = blockIdx.x * blockDim.x + threadIdx.x;
    if (i < LVAL * BVAL * HVAL) out[i] = g_hbuf[0][i];
}
__global__ void embed_kernel(const int* __restrict__ tgt, const float* __restrict__ emb) {
    int row = blockIdx.x;           // t*B + b
    int t = row >> 5, b = row & 31;
    int tok = (t == 0) ? SOS_ID : tgt[b * TVAL + t - 1];
    float4 v = *(const float4*)(emb + (size_t)tok * EVAL + threadIdx.x * 4);
    *(float4*)(g_xall + (size_t)row * EVAL + threadIdx.x * 4) = v;
}

// split fp32 -> bf16 hi/lo, K-extended layout
// A: [hi | lo | hi], a_sel: 0=param, 1=g_xall, 2=g_concats
__global__ void convertA_kernel(const float* __restrict__ Ap, int a_sel, int M) {
    const float* A = (a_sel == 0) ? Ap : (a_sel == 1) ? g_xall : g_concats;
    int i = blockIdx.x * 256 + threadIdx.x;
    if (i >= M * 512) return;
    int m = i >> 9, k = i & 511;
    float w = A[i];
    __nv_bfloat16 hi = __float2bfloat16(w);
    __nv_bfloat16 lo = __float2bfloat16(w - __bfloat162float(hi));
    __nv_bfloat16* dst = g_Asplit + (size_t)m * KSPLIT;
    dst[k] = hi; dst[512 + k] = lo; dst[1024 + k] = hi;
}
// B: [hi | hi | lo]
__global__ void convertB_kernel(const float* __restrict__ W, int N) {
    int i = blockIdx.x * 256 + threadIdx.x;
    if (i >= N * 512) return;
    int n = i >> 9, k = i & 511;
    float w = W[i];
    __nv_bfloat16 hi = __float2bfloat16(w);
    __nv_bfloat16 lo = __float2bfloat16(w - __bfloat162float(hi));
    __nv_bfloat16* dst = g_Bsplit + (size_t)n * KSPLIT;
    dst[k] = hi; dst[512 + k] = hi; dst[1024 + k] = lo;
}

// ---------------- bf16 tensor-core GEMM ----------------
// C[M,N] = g_Asplit[M,K'] @ g_Bsplit[N,K']^T + bias[N],  K'=1536
// Block 128x128, BK=32, 8 warps (warp tile 32x64), double-buffered smem,
// XOR-swizzled 16B chunks for conflict-free ldmatrix.
// c_sel: 0=Cp param, 1=g_encproj, 2=g_gx0
__global__ __launch_bounds__(256, 2) void bgemm_kernel(
    const float* __restrict__ bias, float* __restrict__ Cp,
    int M, int N, int c_sel)
{
    float* C = (c_sel == 0) ? Cp : (c_sel == 1) ? g_encproj : g_gx0;

    __shared__ __align__(16) char smem[32768];
    const unsigned sbase = smem_u32(smem);
    const unsigned bufA[2] = {0u, 16384u};
    const unsigned bufB[2] = {8192u, 24576u};

    const int tid = threadIdx.x;
    const int warp = tid >> 5, lane = tid & 31;
    const int m0 = blockIdx.y * 128;
    const int n0 = blockIdx.x * 128;
    const int wm = (warp & 3) * 32;     // 4 warps along M
    const int wn = (warp >> 2) * 64;    // 2 warps along N

    // ---- global load mapping: 2 chunks of 16B per thread per tile ----
    const int r0g = tid >> 2, cg = tid & 3;     // row 0..63, chunk 0..3
    const int r1g = r0g + 64;
    const unsigned sA0 = swz_off(r0g, cg), sA1 = swz_off(r1g, cg);
    const unsigned sB0 = swz_off(r0g, cg), sB1 = swz_off(r1g, cg);

    const __nv_bfloat16* gA0 = g_Asplit + (size_t)(m0 + r0g) * KSPLIT + cg * 8;
    const __nv_bfloat16* gA1 = g_Asplit + (size_t)(m0 + r1g) * KSPLIT + cg * 8;
    const bool b0ok = (n0 + r0g) < N;
    const bool b1ok = (n0 + r1g) < N;
    const __nv_bfloat16* gB0 = g_Bsplit + (size_t)(b0ok ? n0 + r0g : 0) * KSPLIT + cg * 8;
    const __nv_bfloat16* gB1 = g_Bsplit + (size_t)(b1ok ? n0 + r1g : 0) * KSPLIT + cg * 8;

    // ---- ldmatrix address precompute ----
    const int q = lane >> 3;            // 0..3 (matrix index within x4)
    const int rin = lane & 7;
    const int cq = q >> 1;              // chunk sub-offset within k16
    unsigned relA[2][2], relB[4][2];
#pragma unroll
    for (int mm = 0; mm < 2; mm++) {
        int row = wm + mm * 16 + ((q & 1) << 3) + rin;
        int rsw = (row >> 1) & 3;
#pragma unroll
        for (int kk = 0; kk < 2; kk++)
            relA[mm][kk] = (unsigned)(row * 64 + (((kk * 2 + cq) ^ rsw) << 4));
    }
#pragma unroll
    for (int nh = 0; nh < 4; nh++) {
        int row = wn + nh * 16 + ((q & 1) << 3) + rin;
        int rsw = (row >> 1) & 3;
#pragma unroll
        for (int kk = 0; kk < 2; kk++)
            relB[nh][kk] = (unsigned)(row * 64 + (((kk * 2 + cq) ^ rsw) << 4));
    }

    float acc[2][8][4];
#pragma unroll
    for (int i = 0; i < 2; i++)
#pragma unroll
        for (int j = 0; j < 8; j++)
#pragma unroll
            for (int c = 0; c < 4; c++) acc[i][j][c] = 0.f;

    const uint4 z4 = make_uint4(0u, 0u, 0u, 0u);
    uint4 av0 = *(const uint4*)gA0;
    uint4 av1 = *(const uint4*)gA1;
    uint4 bv0 = b0ok ? *(const uint4*)gB0 : z4;
    uint4 bv1 = b1ok ? *(const uint4*)gB1 : z4;
    *(uint4*)(smem + bufA[0] + sA0) = av0;
    *(uint4*)(smem + bufA[0] + sA1) = av1;
    *(uint4*)(smem + bufB[0] + sB0) = bv0;
    *(uint4*)(smem + bufB[0] + sB1) = bv1;
    __syncthreads();

    const int nk = KSPLIT / 32;         // 48
    for (int kt = 0; kt < nk; kt++) {
        const int cur = kt & 1;
        const bool more = (kt + 1) < nk;
        if (more) {
            const int ko = (kt + 1) * 32;
            av0 = *(const uint4*)(gA0 + ko);
            av1 = *(const uint4*)(gA1 + ko);
            bv0 = b0ok ? *(const uint4*)(gB0 + ko) : z4;
            bv1 = b1ok ? *(const uint4*)(gB1 + ko) : z4;
        }
        const unsigned bA = sbase + bufA[cur];
        const unsigned bB = sbase + bufB[cur];
#pragma unroll
        for (int kk = 0; kk < 2; kk++) {
            unsigned ra[2][4];
            LDSM4(ra[0][0], ra[0][1], ra[0][2], ra[0][3], bA + relA[0][kk]);
            LDSM4(ra[1][0], ra[1][1], ra[1][2], ra[1][3], bA + relA[1][kk]);
#pragma unroll
            for (int nh = 0; nh < 4; nh++) {
                unsigned rb0, rb1, rb2, rb3;
                LDSM4(rb0, rb1, rb2, rb3, bB + relB[nh][kk]);
                MMA16816(acc[0][2 * nh],     ra[0][0], ra[0][1], ra[0][2], ra[0][3], rb0, rb2);
                MMA16816(acc[1][2 * nh],     ra[1][0], ra[1][1], ra[1][2], ra[1][3], rb0, rb2);
                MMA16816(acc[0][2 * nh + 1], ra[0][0], ra[0][1], ra[0][2], ra[0][3], rb1, rb3);
                MMA16816(acc[1][2 * nh + 1], ra[1][0], ra[1][1], ra[1][2], ra[1][3], rb1, rb3);
            }
        }
        if (more) {
            const int nx = cur ^ 1;
            *(uint4*)(smem + bufA[nx] + sA0) = av0;
            *(uint4*)(smem + bufA[nx] + sA1) = av1;
            *(uint4*)(smem + bufB[nx] + sB0) = bv0;
            *(uint4*)(smem + bufB[nx] + sB1) = bv1;
        }
        __syncthreads();
    }

    // ---- epilogue ----
    const int trow = lane >> 2;
    const int tcol = (lane & 3) * 2;
#pragma unroll
    for (int mm = 0; mm < 2; mm++) {
#pragma unroll
        for (int nn = 0; nn < 8; nn++) {
            int r = m0 + wm + mm * 16 + trow;
            int cb = n0 + wn + nn * 8 + tcol;
            float* cr0 = C + (size_t)r * N;
            float* cr1 = C + (size_t)(r + 8) * N;
            if (cb < N) {
                cr0[cb] = acc[mm][nn][0] + bias[cb];
                cr1[cb] = acc[mm][nn][2] + bias[cb];
            }
            if (cb + 1 < N) {
                cr0[cb + 1] = acc[mm][nn][1] + bias[cb + 1];
                cr1[cb + 1] = acc[mm][nn][3] + bias[cb + 1];
            }
        }
    }
}

// ---------------- fused GRU step (one layer) ----------------
template <bool HAS_X>
__global__ __launch_bounds__(128) void gru_step_kernel(
    const float* __restrict__ Wih, const float* __restrict__ Whh,
    const float* __restrict__ bih, const float* __restrict__ bhh,
    int t, int layer, int buf_in, int buf_out)
{
    constexpr int PER = HAS_X ? 6 : 3;
    __shared__ float h_s[32][133];
    __shared__ float x_s[HAS_X ? 32 : 1][133];
    __shared__ float w_s[PER * 4][128];

    const int tid = threadIdx.x;
    const int warp = tid >> 5, lane = tid & 31;
    const int j = blockIdx.x * 4 + warp;
    const int b = lane;

    const float* h_in = g_hbuf[buf_in] + layer * BVAL * HVAL;
    const float* x_in = g_hbuf[buf_out];
    float* h_out = g_hbuf[buf_out] + layer * BVAL * HVAL;

    float ar = 0.f, az = 0.f, an = 0.f;
    float xr = 0.f, xz = 0.f, xn = 0.f;

    for (int k0 = 0; k0 < HVAL; k0 += 128) {
#pragma unroll
        for (int it = 0; it < 8; ++it) {
            int flat = tid + it * 128;
            int bb = flat >> 5, kq = flat & 31;
            float4 v = *(const float4*)(h_in + bb * HVAL + k0 + kq * 4);
            h_s[bb][kq * 4 + 0] = v.x; h_s[bb][kq * 4 + 1] = v.y;
            h_s[bb][kq * 4 + 2] = v.z; h_s[bb][kq * 4 + 3] = v.w;
            if (HAS_X) {
                float4 u = *(const float4*)(x_in + bb * HVAL + k0 + kq * 4);
                x_s[bb][kq * 4 + 0] = u.x; x_s[bb][kq * 4 + 1] = u.y;
                x_s[bb][kq * 4 + 2] = u.z; x_s[bb][kq * 4 + 3] = u.w;
            }
        }
#pragma unroll
        for (int it = 0; it < PER; ++it) {
            int flat = tid + it * 128;
            int r = flat >> 5, kq = flat & 31;
            int jl = r / PER, which = r % PER;
            int jj = blockIdx.x * 4 + jl;
            const float* src;
            if (HAS_X)
                src = (which < 3) ? (Wih + ((size_t)(which * HVAL + jj)) * HVAL)
                                  : (Whh + ((size_t)((which - 3) * HVAL + jj)) * HVAL);
            else
                src = Whh + ((size_t)(which * HVAL + jj)) * HVAL;
            float4 w = *(const float4*)(src + k0 + kq * 4);
            w_s[r][kq * 4 + 0] = w.x; w_s[r][kq * 4 + 1] = w.y;
            w_s[r][kq * 4 + 2] = w.z; w_s[r][kq * 4 + 3] = w.w;
        }
        __syncthreads();
        const int wb = warp * PER;
#pragma unroll 4
        for (int k = 0; k < 128; k++) {
            float hv = h_s[b][k];
            if (HAS_X) {
                float xv = x_s[b][k];
                xr = fmaf(w_s[wb + 0][k], xv, xr);
                xz = fmaf(w_s[wb + 1][k], xv, xz);
                xn = fmaf(w_s[wb + 2][k], xv, xn);
                ar = fmaf(w_s[wb + 3][k], hv, ar);
                az = fmaf(w_s[wb + 4][k], hv, az);
                an = fmaf(w_s[wb + 5][k], hv, an);
            } else {
                ar = fmaf(w_s[wb + 0][k], hv, ar);
                az = fmaf(w_s[wb + 1][k], hv, az);
                an = fmaf(w_s[wb + 2][k], hv, an);
            }
        }
        __syncthreads();
    }

    float gxr, gxz, gxn;
    if (HAS_X) {
        gxr = xr + bih[j]; gxz = xz + bih[HVAL + j]; gxn = xn + bih[2 * HVAL + j];
    } else {
        const float* g = g_gx0 + ((size_t)(t * BVAL + b)) * 3 * HVAL;
        gxr = g[j]; gxz = g[HVAL + j]; gxn = g[2 * HVAL + j];
    }
    float ghr = ar + bhh[j];
    float ghz = az + bhh[HVAL + j];
    float ghn = an + bhh[2 * HVAL + j];
    float rg = 1.f / (1.f + __expf(-(gxr + ghr)));
    float zg = 1.f / (1.f + __expf(-(gxz + ghz)));
    float ng = tanhf(gxn + rg * ghn);
    h_out[b * HVAL + j] = (1.f - zg) * ng + zg * h_in[b * HVAL + j];
}

// ---------------- attention ----------------
__global__ __launch_bounds__(128) void attn_kernel(
    const float* __restrict__ enc, const unsigned char* __restrict__ mask, int hb)
{
    const int b = blockIdx.x;
    const int tid = threadIdx.x;
    const int warp = tid >> 5, lane = tid & 31;
    const float* h1 = g_hbuf[hb] + BVAL * HVAL;

    __shared__ float hs[HVAL];
    __shared__ float sc[SVAL];
    __shared__ float red[4];

    ((float4*)hs)[tid] = *(const float4*)(h1 + b * HVAL + tid * 4);
    __syncthreads();

    for (int s = warp; s < SVAL; s += 4) {
        const float* ep = g_encproj + ((size_t)(s * BVAL + b)) * HVAL;
        float p = 0.f;
#pragma unroll 4
        for (int k = lane; k < HVAL; k += 32) p = fmaf(hs[k], ep[k], p);
#pragma unroll
        for (int o = 16; o > 0; o >>= 1) p += __shfl_down_sync(0xffffffffu, p, o);
        if (lane == 0) sc[s] = mask[b * SVAL + s] ? -1e9f : p;
    }
    __syncthreads();

    float v = sc[tid];
    float m = v;
#pragma unroll
    for (int o = 16; o > 0; o >>= 1) m = fmaxf(m, __shfl_xor_sync(0xffffffffu, m, o));
    if (lane == 0) red[warp] = m;
    __syncthreads();
    m = fmaxf(fmaxf(red[0], red[1]), fmaxf(red[2], red[3]));
    __syncthreads();
    float e = __expf(v - m);
    float s = e;
#pragma unroll
    for (int o = 16; o > 0; o >>= 1) s += __shfl_xor_sync(0xffffffffu, s, o);
    if (lane == 0) red[warp] = s;
    __syncthreads();
    s = red[0] + red[1] + red[2] + red[3];
    sc[tid] = e / s;
    __syncthreads();

    for (int hh = tid; hh < HVAL; hh += 128) {
        float acc = 0.f;
#pragma unroll 4
        for (int ss = 0; ss < SVAL; ss++)
            acc = fmaf(sc[ss], enc[((size_t)(ss * BVAL + b)) * HVAL + hh], acc);
        g_ctx[b * HVAL + hh] = acc;
    }
}

// ---------------- concat projection ----------------
__global__ __launch_bounds__(128) void concat_kernel(
    const float* __restrict__ Wc, const float* __restrict__ bc, int t, int hb)
{
    __shared__ float c_s[32][133];
    __shared__ float w_s[4][128];
    const int tid = threadIdx.x;
    const int warp = tid >> 5, lane = tid & 31;
    const int j = blockIdx.x * 4 + warp;
    const int b = lane;
    const float* h1 = g_hbuf[hb] + BVAL * HVAL;

    float acc = 0.f;
    for (int k0 = 0; k0 < 2 * HVAL; k0 += 128) {
#pragma unroll
        for (int it = 0; it < 8; ++it) {
            int flat = tid + it * 128;
            int bb = flat >> 5, kq = flat & 31;
            int k = k0 + kq * 4;
            const float* src = (k < HVAL) ? (g_ctx + bb * HVAL + k)
                                          : (h1 + bb * HVAL + (k - HVAL));
            float4 v = *(const float4*)src;
            c_s[bb][kq * 4 + 0] = v.x; c_s[bb][kq * 4 + 1] = v.y;
            c_s[bb][kq * 4 + 2] = v.z; c_s[bb][kq * 4 + 3] = v.w;
        }
        {
            int r = tid >> 5, kq = tid & 31;
            float4 w = *(const float4*)(Wc + ((size_t)(blockIdx.x * 4 + r)) * 2 * HVAL + k0 + kq * 4);
            w_s[r][kq * 4 + 0] = w.x; w_s[r][kq * 4 + 1] = w.y;
            w_s[r][kq * 4 + 2] = w.z; w_s[r][kq * 4 + 3] = w.w;
        }
        __syncthreads();
#pragma unroll 4
        for (int k = 0; k < 128; k++)
            acc = fmaf(w_s[warp][k], c_s[b][k], acc);
        __syncthreads();
    }
    g_concats[((size_t)(t * BVAL + b)) * HVAL + j] = tanhf(acc + bc[j]);
}

// ---------------- launcher ----------------
extern "C" void kernel_launch(void* const* d_in, const int* in_sizes, int n_in,
                              void* d_out, int out_size) {
    const int* tgt            = (const int*)d_in[0];
    const float* dh           = (const float*)d_in[1];
    const float* enc          = (const float*)d_in[2];
    const unsigned char* mask = (const unsigned char*)d_in[3];
    const float* emb          = (const float*)d_in[4];
    const float* Wih          = (const float*)d_in[5];
    const float* Whh          = (const float*)d_in[6];
    const float* bih          = (const float*)d_in[7];
    const float* bhh          = (const float*)d_in[8];
    const float* Wa           = (const float*)d_in[9];
    const float* ba           = (const float*)d_in[10];
    const float* Wc           = (const float*)d_in[11];
    const float* bc           = (const float*)d_in[12];
    const float* Ws           = (const float*)d_in[13];
    const float* bs           = (const float*)d_in[14];
    float* out = (float*)d_out;

    init_h_kernel<<<(LVAL * BVAL * HVAL + 255) / 256, 256>>>(dh);
    embed_kernel<<<TVAL * BVAL, 128>>>(tgt, emb);

    // enc_proj = enc @ Wa^T + ba   (M=4096, N=512)
    convertB_kernel<<<(HVAL * 512 + 255) / 256, 256>>>(Wa, HVAL);
    convertA_kernel<<<(4096 * 512 + 255) / 256, 256>>>(enc, 0, SVAL * BVAL);
    bgemm_kernel<<<dim3((HVAL + 127) / 128, (SVAL * BVAL) / 128), 256>>>(
        ba, nullptr, SVAL * BVAL, HVAL, 1);

    // gx0 = x_all @ Wih0^T + bih0  (M=1024, N=1536)
    convertB_kernel<<<(3 * HVAL * 512 + 255) / 256, 256>>>(Wih, 3 * HVAL);
    convertA_kernel<<<(1024 * 512 + 255) / 256, 256>>>(nullptr, 1, TVAL * BVAL);
    bgemm_kernel<<<dim3((3 * HVAL + 127) / 128, (TVAL * BVAL) / 128), 256>>>(
        bih, nullptr, TVAL * BVAL, 3 * HVAL, 2);

    // split Ws now (g_Bsplit free after gx0 gemm); overlaps with recurrence
    convertB_kernel<<<(VVAL * 512 + 255) / 256, 256>>>(Ws, VVAL);

    // recurrence
    for (int t = 0; t < TVAL; t++) {
        int bin = t & 1, bout = (t + 1) & 1;
        gru_step_kernel<false><<<128, 128>>>(nullptr, Whh, nullptr, bhh, t, 0, bin, bout);
        gru_step_kernel<true><<<128, 128>>>(Wih + 3 * HVAL * EVAL, Whh + 3 * HVAL * HVAL,
                                            bih + 3 * HVAL, bhh + 3 * HVAL, t, 1, bin, bout);
        attn_kernel<<<BVAL, 128>>>(enc, mask, bout);
        concat_kernel<<<128, 128>>>(Wc, bc, t, bout);
    }

    // decoder_outputs = concats @ Ws^T + bs  (M=1024, N=50257)
    convertA_kernel<<<(1024 * 512 + 255) / 256, 256>>>(nullptr, 2, TVAL * BVAL);
    bgemm_kernel<<<dim3((VVAL + 127) / 128, (TVAL * BVAL) / 128), 256>>>(
        bs, out, TVAL * BVAL, VVAL, 0);

    // h_final tail
    long main_elems = (long)TVAL * BVAL * VVAL;
    if ((long)out_size >= main_elems + (long)LVAL * BVAL * HVAL)
        final_h_kernel<<<128, 256>>>(out + main_elems);
}

// round 6
// speedup vs baseline: 1.1505x; 1.0015x over previous
#include <cuda_runtime.h>
#include <cuda_bf16.h>
#include <math.h>

#define BVAL 32
#define TVAL 32
#define SVAL 128
#define HVAL 512
#define EVAL 512
#define VVAL 50257
#define LVAL 2
#define SOS_ID 1
#define KSPLIT 1536   // [hi | lo | hi] x [hi | hi | lo]
#define STAGES 3
#define NKT (KSPLIT / 32)   // 48 k-tiles of 32

// ---------------- scratch (device globals; no runtime allocation) ----------------
__device__ float g_encproj[SVAL * BVAL * HVAL];        // (s*B+b, H)
__device__ float g_xall[TVAL * BVAL * EVAL];           // (t*B+b, E)
__device__ float g_gx0[TVAL * BVAL * 3 * HVAL];        // (t*B+b, 3H)
__device__ float g_hbuf[2][LVAL * BVAL * HVAL];        // ping-pong hidden state
__device__ float g_ctx[BVAL * HVAL];
__device__ float g_concats[TVAL * BVAL * HVAL];
__device__ __nv_bfloat16 g_Asplit[4096 * KSPLIT];      // split activations (max M=4096)
__device__ __nv_bfloat16 g_Bsplit[VVAL * KSPLIT];      // split weights (max N=V)

__device__ __forceinline__ unsigned smem_u32(const void* p) {
    unsigned a;
    asm("{ .reg .u64 t; cvta.to.shared.u64 t, %1; cvt.u32.u64 %0, t; }" : "=r"(a) : "l"(p));
    return a;
}

// swizzled smem byte offset for a (row, 16B-chunk) within a 128x32 bf16 tile
__device__ __forceinline__ unsigned swz_off(int row, int chunk) {
    return (unsigned)(row * 64 + ((chunk ^ ((row >> 1) & 3)) << 4));
}

#define LDSM4(R0,R1,R2,R3,ADDR) \
    asm volatile("ldmatrix.sync.aligned.m8n8.x4.shared.b16 {%0,%1,%2,%3}, [%4];" \
        : "=r"(R0),"=r"(R1),"=r"(R2),"=r"(R3) : "r"(ADDR))

#define MMA16816(D,A0,A1,A2,A3,B0,B1) \
    asm volatile("mma.sync.aligned.m16n8k16.row.col.f32.bf16.bf16.f32 " \
        "{%0,%1,%2,%3}, {%4,%5,%6,%7}, {%8,%9}, {%0,%1,%2,%3};" \
        : "+f"(D[0]),"+f"(D[1]),"+f"(D[2]),"+f"(D[3]) \
        : "r"(A0),"r"(A1),"r"(A2),"r"(A3),"r"(B0),"r"(B1))

#define CP_ASYNC16(DST,SRC) \
    asm volatile("cp.async.cg.shared.global [%0], [%1], 16;" \
        :: "r"(DST), "l"(SRC) : "memory")
#define CP_ASYNC16_Z(DST,SRC,SZ) \
    asm volatile("cp.async.cg.shared.global [%0], [%1], 16, %2;" \
        :: "r"(DST), "l"(SRC), "r"(SZ) : "memory")

// ---------------- small kernels ----------------
__global__ void init_h_kernel(const float* __restrict__ dh) {
    int i = blockIdx.x * blockDim.x + threadIdx.x;
    if (i < LVAL * BVAL * HVAL) g_hbuf[0][i] = dh[i];
}
__global__ void final_h_kernel(float* __restrict__ out) {
    int i = blockIdx.x * blockDim.x + threadIdx.x;
    if (i < LVAL * BVAL * HVAL) out[i] = g_hbuf[0][i];
}
__global__ void embed_kernel(const int* __restrict__ tgt, const float* __restrict__ emb) {
    int row = blockIdx.x;           // t*B + b
    int t = row >> 5, b = row & 31;
    int tok = (t == 0) ? SOS_ID : tgt[b * TVAL + t - 1];
    float4 v = *(const float4*)(emb + (size_t)tok * EVAL + threadIdx.x * 4);
    *(float4*)(g_xall + (size_t)row * EVAL + threadIdx.x * 4) = v;
}

// split fp32 -> bf16 hi/lo, K-extended layout
// A: [hi | lo | hi], a_sel: 0=param, 1=g_xall, 2=g_concats
__global__ void convertA_kernel(const float* __restrict__ Ap, int a_sel, int M) {
    const float* A = (a_sel == 0) ? Ap : (a_sel == 1) ? g_xall : g_concats;
    int i = blockIdx.x * 256 + threadIdx.x;
    if (i >= M * 512) return;
    int m = i >> 9, k = i & 511;
    float w = A[i];
    __nv_bfloat16 hi = __float2bfloat16(w);
    __nv_bfloat16 lo = __float2bfloat16(w - __bfloat162float(hi));
    __nv_bfloat16* dst = g_Asplit + (size_t)m * KSPLIT;
    dst[k] = hi; dst[512 + k] = lo; dst[1024 + k] = hi;
}
// B: [hi | hi | lo]
__global__ void convertB_kernel(const float* __restrict__ W, int N) {
    int i = blockIdx.x * 256 + threadIdx.x;
    if (i >= N * 512) return;
    int n = i >> 9, k = i & 511;
    float w = W[i];
    __nv_bfloat16 hi = __float2bfloat16(w);
    __nv_bfloat16 lo = __float2bfloat16(w - __bfloat162float(hi));
    __nv_bfloat16* dst = g_Bsplit + (size_t)n * KSPLIT;
    dst[k] = hi; dst[512 + k] = hi; dst[1024 + k] = lo;
}

// ---------------- bf16 tensor-core GEMM (mma.sync + cp.async pipeline) ----------
// C[M,N] = g_Asplit[M,K'] @ g_Bsplit[N,K']^T + bias[N],  K'=1536
// Block 128x128, BK=32, 3-stage cp.async pipeline, 8 warps (warp tile 32x64),
// XOR-swizzled 16B chunks for conflict-free ldmatrix. Grid is M-fastest so the
// 8 M-tiles sharing a B slab run concurrently (B streamed from DRAM once).
// c_sel: 0=Cp param, 1=g_encproj, 2=g_gx0
__device__ __forceinline__ void ld_tile_async(unsigned sbase, int st, int kc,
                                              int m0, int n0, int N, int tid)
{
    const unsigned abuf = sbase + (unsigned)st * 16384u;
    const unsigned bbuf = abuf + 8192u;
    const int r0 = tid >> 2, cg = tid & 3;
    const int koff = kc * 32 + cg * 8;
#pragma unroll
    for (int h = 0; h < 2; h++) {
        const int row = r0 + h * 64;
        const unsigned off = swz_off(row, cg);
        const __nv_bfloat16* sa = g_Asplit + (size_t)(m0 + row) * KSPLIT + koff;
        CP_ASYNC16(abuf + off, __cvta_generic_to_global(sa));
        const int brow = n0 + row;
        const __nv_bfloat16* sb = g_Bsplit + (size_t)(brow < N ? brow : 0) * KSPLIT + koff;
        CP_ASYNC16_Z(bbuf + off, __cvta_generic_to_global(sb), (brow < N) ? 16 : 0);
    }
}

__global__ __launch_bounds__(256, 2) void bgemm_kernel(
    const float* __restrict__ bias, float* __restrict__ Cp,
    int M, int N, int c_sel)
{
    float* C = (c_sel == 0) ? Cp : (c_sel == 1) ? g_encproj : g_gx0;

    __shared__ __align__(16) char smem[STAGES * 16384];
    const unsigned sbase = smem_u32(smem);

    const int tid = threadIdx.x;
    const int warp = tid >> 5, lane = tid & 31;
    const int m0 = blockIdx.x * 128;            // M fastest
    const int n0 = blockIdx.y * 128;
    const int wm = (warp & 3) * 32;             // 4 warps along M
    const int wn = (warp >> 2) * 64;            // 2 warps along N

    // ---- ldmatrix address precompute (verified layout from R3) ----
    const int q = lane >> 3;
    const int rin = lane & 7;
    const int cq = q >> 1;
    unsigned relA[2][2], relB[4][2];
#pragma unroll
    for (int mm = 0; mm < 2; mm++) {
        int row = wm + mm * 16 + ((q & 1) << 3) + rin;
        int rsw = (row >> 1) & 3;
#pragma unroll
        for (int kk = 0; kk < 2; kk++)
            relA[mm][kk] = (unsigned)(row * 64 + (((kk * 2 + cq) ^ rsw) << 4));
    }
#pragma unroll
    for (int nh = 0; nh < 4; nh++) {
        int row = wn + nh * 16 + ((q & 1) << 3) + rin;
        int rsw = (row >> 1) & 3;
#pragma unroll
        for (int kk = 0; kk < 2; kk++)
            relB[nh][kk] = (unsigned)(row * 64 + (((kk * 2 + cq) ^ rsw) << 4));
    }

    float acc[2][8][4];
#pragma unroll
    for (int i = 0; i < 2; i++)
#pragma unroll
        for (int j = 0; j < 8; j++)
#pragma unroll
            for (int c = 0; c < 4; c++) acc[i][j][c] = 0.f;

    // prologue: fill STAGES-1 buffers
#pragma unroll
    for (int s = 0; s < STAGES - 1; s++) {
        ld_tile_async(sbase, s, s, m0, n0, N, tid);
        asm volatile("cp.async.commit_group;" ::: "memory");
    }

    for (int kt = 0; kt < NKT; kt++) {
        if (kt == NKT - 1) asm volatile("cp.async.wait_group 0;" ::: "memory");
        else               asm volatile("cp.async.wait_group 1;" ::: "memory");
        __syncthreads();

        const int nl = kt + STAGES - 1;
        if (nl < NKT) {
            ld_tile_async(sbase, nl % STAGES, nl, m0, n0, N, tid);
            asm volatile("cp.async.commit_group;" ::: "memory");
        }

        const unsigned bA = sbase + (unsigned)(kt % STAGES) * 16384u;
        const unsigned bB = bA + 8192u;
#pragma unroll
        for (int kk = 0; kk < 2; kk++) {
            unsigned ra[2][4];
            LDSM4(ra[0][0], ra[0][1], ra[0][2], ra[0][3], bA + relA[0][kk]);
            LDSM4(ra[1][0], ra[1][1], ra[1][2], ra[1][3], bA + relA[1][kk]);
#pragma unroll
            for (int nh = 0; nh < 4; nh++) {
                unsigned rb0, rb1, rb2, rb3;
                LDSM4(rb0, rb1, rb2, rb3, bB + relB[nh][kk]);
                MMA16816(acc[0][2 * nh],     ra[0][0], ra[0][1], ra[0][2], ra[0][3], rb0, rb2);
                MMA16816(acc[1][2 * nh],     ra[1][0], ra[1][1], ra[1][2], ra[1][3], rb0, rb2);
                MMA16816(acc[0][2 * nh + 1], ra[0][0], ra[0][1], ra[0][2], ra[0][3], rb1, rb3);
                MMA16816(acc[1][2 * nh + 1], ra[1][0], ra[1][1], ra[1][2], ra[1][3], rb1, rb3);
            }
        }
        __syncthreads();
    }

    // ---- epilogue (32B-segment coalesced direct stores) ----
    const int trow = lane >> 2;
    const int tcol = (lane & 3) * 2;
#pragma unroll
    for (int mm = 0; mm < 2; mm++) {
#pragma unroll
        for (int nn = 0; nn < 8; nn++) {
            int r = m0 + wm + mm * 16 + trow;
            int cb = n0 + wn + nn * 8 + tcol;
            float* cr0 = C + (size_t)r * N;
            float* cr1 = C + (size_t)(r + 8) * N;
            if (cb < N) {
                cr0[cb] = acc[mm][nn][0] + bias[cb];
                cr1[cb] = acc[mm][nn][2] + bias[cb];
            }
            if (cb + 1 < N) {
                cr0[cb + 1] = acc[mm][nn][1] + bias[cb + 1];
                cr1[cb + 1] = acc[mm][nn][3] + bias[cb + 1];
            }
        }
    }
}

// ---------------- fused GRU step (one layer) ----------------
template <bool HAS_X>
__global__ __launch_bounds__(128) void gru_step_kernel(
    const float* __restrict__ Wih, const float* __restrict__ Whh,
    const float* __restrict__ bih, const float* __restrict__ bhh,
    int t, int layer, int buf_in, int buf_out)
{
    constexpr int PER = HAS_X ? 6 : 3;
    __shared__ float h_s[32][133];
    __shared__ float x_s[HAS_X ? 32 : 1][133];
    __shared__ float w_s[PER * 4][128];

    const int tid = threadIdx.x;
    const int warp = tid >> 5, lane = tid & 31;
    const int j = blockIdx.x * 4 + warp;
    const int b = lane;

    const float* h_in = g_hbuf[buf_in] + layer * BVAL * HVAL;
    const float* x_in = g_hbuf[buf_out];
    float* h_out = g_hbuf[buf_out] + layer * BVAL * HVAL;

    float ar = 0.f, az = 0.f, an = 0.f;
    float xr = 0.f, xz = 0.f, xn = 0.f;

    for (int k0 = 0; k0 < HVAL; k0 += 128) {
#pragma unroll
        for (int it = 0; it < 8; ++it) {
            int flat = tid + it * 128;
            int bb = flat >> 5, kq = flat & 31;
            float4 v = *(const float4*)(h_in + bb * HVAL + k0 + kq * 4);
            h_s[bb][kq * 4 + 0] = v.x; h_s[bb][kq * 4 + 1] = v.y;
            h_s[bb][kq * 4 + 2] = v.z; h_s[bb][kq * 4 + 3] = v.w;
            if (HAS_X) {
                float4 u = *(const float4*)(x_in + bb * HVAL + k0 + kq * 4);
                x_s[bb][kq * 4 + 0] = u.x; x_s[bb][kq * 4 + 1] = u.y;
                x_s[bb][kq * 4 + 2] = u.z; x_s[bb][kq * 4 + 3] = u.w;
            }
        }
#pragma unroll
        for (int it = 0; it < PER; ++it) {
            int flat = tid + it * 128;
            int r = flat >> 5, kq = flat & 31;
            int jl = r / PER, which = r % PER;
            int jj = blockIdx.x * 4 + jl;
            const float* src;
            if (HAS_X)
                src = (which < 3) ? (Wih + ((size_t)(which * HVAL + jj)) * HVAL)
                                  : (Whh + ((size_t)((which - 3) * HVAL + jj)) * HVAL);
            else
                src = Whh + ((size_t)(which * HVAL + jj)) * HVAL;
            float4 w = *(const float4*)(src + k0 + kq * 4);
            w_s[r][kq * 4 + 0] = w.x; w_s[r][kq * 4 + 1] = w.y;
            w_s[r][kq * 4 + 2] = w.z; w_s[r][kq * 4 + 3] = w.w;
        }
        __syncthreads();
        const int wb = warp * PER;
#pragma unroll 4
        for (int k = 0; k < 128; k++) {
            float hv = h_s[b][k];
            if (HAS_X) {
                float xv = x_s[b][k];
                xr = fmaf(w_s[wb + 0][k], xv, xr);
                xz = fmaf(w_s[wb + 1][k], xv, xz);
                xn = fmaf(w_s[wb + 2][k], xv, xn);
                ar = fmaf(w_s[wb + 3][k], hv, ar);
                az = fmaf(w_s[wb + 4][k], hv, az);
                an = fmaf(w_s[wb + 5][k], hv, an);
            } else {
                ar = fmaf(w_s[wb + 0][k], hv, ar);
                az = fmaf(w_s[wb + 1][k], hv, az);
                an = fmaf(w_s[wb + 2][k], hv, an);
            }
        }
        __syncthreads();
    }

    float gxr, gxz, gxn;
    if (HAS_X) {
        gxr = xr + bih[j]; gxz = xz + bih[HVAL + j]; gxn = xn + bih[2 * HVAL + j];
    } else {
        const float* g = g_gx0 + ((size_t)(t * BVAL + b)) * 3 * HVAL;
        gxr = g[j]; gxz = g[HVAL + j]; gxn = g[2 * HVAL + j];
    }
    float ghr = ar + bhh[j];
    float ghz = az + bhh[HVAL + j];
    float ghn = an + bhh[2 * HVAL + j];
    float rg = 1.f / (1.f + __expf(-(gxr + ghr)));
    float zg = 1.f / (1.f + __expf(-(gxz + ghz)));
    float ng = tanhf(gxn + rg * ghn);
    h_out[b * HVAL + j] = (1.f - zg) * ng + zg * h_in[b * HVAL + j];
}

// ---------------- attention ----------------
__global__ __launch_bounds__(128) void attn_kernel(
    const float* __restrict__ enc, const unsigned char* __restrict__ mask, int hb)
{
    const int b = blockIdx.x;
    const int tid = threadIdx.x;
    const int warp = tid >> 5, lane = tid & 31;
    const float* h1 = g_hbuf[hb] + BVAL * HVAL;

    __shared__ float hs[HVAL];
    __shared__ float sc[SVAL];
    __shared__ float red[4];

    ((float4*)hs)[tid] = *(const float4*)(h1 + b * HVAL + tid * 4);
    __syncthreads();

    for (int s = warp; s < SVAL; s += 4) {
        const float* ep = g_encproj + ((size_t)(s * BVAL + b)) * HVAL;
        float p = 0.f;
#pragma unroll 4
        for (int k = lane; k < HVAL; k += 32) p = fmaf(hs[k], ep[k], p);
#pragma unroll
        for (int o = 16; o > 0; o >>= 1) p += __shfl_down_sync(0xffffffffu, p, o);
        if (lane == 0) sc[s] = mask[b * SVAL + s] ? -1e9f : p;
    }
    __syncthreads();

    float v = sc[tid];
    float m = v;
#pragma unroll
    for (int o = 16; o > 0; o >>= 1) m = fmaxf(m, __shfl_xor_sync(0xffffffffu, m, o));
    if (lane == 0) red[warp] = m;
    __syncthreads();
    m = fmaxf(fmaxf(red[0], red[1]), fmaxf(red[2], red[3]));
    __syncthreads();
    float e = __expf(v - m);
    float s = e;
#pragma unroll
    for (int o = 16; o > 0; o >>= 1) s += __shfl_xor_sync(0xffffffffu, s, o);
    if (lane == 0) red[warp] = s;
    __syncthreads();
    s = red[0] + red[1] + red[2] + red[3];
    sc[tid] = e / s;
    __syncthreads();

    for (int hh = tid; hh < HVAL; hh += 128) {
        float acc = 0.f;
#pragma unroll 4
        for (int ss = 0; ss < SVAL; ss++)
            acc = fmaf(sc[ss], enc[((size_t)(ss * BVAL + b)) * HVAL + hh], acc);
        g_ctx[b * HVAL + hh] = acc;
    }
}

// ---------------- concat projection ----------------
__global__ __launch_bounds__(128) void concat_kernel(
    const float* __restrict__ Wc, const float* __restrict__ bc, int t, int hb)
{
    __shared__ float c_s[32][133];
    __shared__ float w_s[4][128];
    const int tid = threadIdx.x;
    const int warp = tid >> 5, lane = tid & 31;
    const int j = blockIdx.x * 4 + warp;
    const int b = lane;
    const float* h1 = g_hbuf[hb] + BVAL * HVAL;

    float acc = 0.f;
    for (int k0 = 0; k0 < 2 * HVAL; k0 += 128) {
#pragma unroll
        for (int it = 0; it < 8; ++it) {
            int flat = tid + it * 128;
            int bb = flat >> 5, kq = flat & 31;
            int k = k0 + kq * 4;
            const float* src = (k < HVAL) ? (g_ctx + bb * HVAL + k)
                                          : (h1 + bb * HVAL + (k - HVAL));
            float4 v = *(const float4*)src;
            c_s[bb][kq * 4 + 0] = v.x; c_s[bb][kq * 4 + 1] = v.y;
            c_s[bb][kq * 4 + 2] = v.z; c_s[bb][kq * 4 + 3] = v.w;
        }
        {
            int r = tid >> 5, kq = tid & 31;
            float4 w = *(const float4*)(Wc + ((size_t)(blockIdx.x * 4 + r)) * 2 * HVAL + k0 + kq * 4);
            w_s[r][kq * 4 + 0] = w.x; w_s[r][kq * 4 + 1] = w.y;
            w_s[r][kq * 4 + 2] = w.z; w_s[r][kq * 4 + 3] = w.w;
        }
        __syncthreads();
#pragma unroll 4
        for (int k = 0; k < 128; k++)
            acc = fmaf(w_s[warp][k], c_s[b][k], acc);
        __syncthreads();
    }
    g_concats[((size_t)(t * BVAL + b)) * HVAL + j] = tanhf(acc + bc[j]);
}

// ---------------- launcher ----------------
extern "C" void kernel_launch(void* const* d_in, const int* in_sizes, int n_in,
                              void* d_out, int out_size) {
    const int* tgt            = (const int*)d_in[0];
    const float* dh           = (const float*)d_in[1];
    const float* enc          = (const float*)d_in[2];
    const unsigned char* mask = (const unsigned char*)d_in[3];
    const float* emb          = (const float*)d_in[4];
    const float* Wih          = (const float*)d_in[5];
    const float* Whh          = (const float*)d_in[6];
    const float* bih          = (const float*)d_in[7];
    const float* bhh          = (const float*)d_in[8];
    const float* Wa           = (const float*)d_in[9];
    const float* ba           = (const float*)d_in[10];
    const float* Wc           = (const float*)d_in[11];
    const float* bc           = (const float*)d_in[12];
    const float* Ws           = (const float*)d_in[13];
    const float* bs           = (const float*)d_in[14];
    float* out = (float*)d_out;

    init_h_kernel<<<(LVAL * BVAL * HVAL + 255) / 256, 256>>>(dh);
    embed_kernel<<<TVAL * BVAL, 128>>>(tgt, emb);

    // enc_proj = enc @ Wa^T + ba   (M=4096, N=512)
    convertB_kernel<<<(HVAL * 512 + 255) / 256, 256>>>(Wa, HVAL);
    convertA_kernel<<<(4096 * 512 + 255) / 256, 256>>>(enc, 0, SVAL * BVAL);
    bgemm_kernel<<<dim3((SVAL * BVAL) / 128, HVAL / 128), 256>>>(
        ba, nullptr, SVAL * BVAL, HVAL, 1);

    // gx0 = x_all @ Wih0^T + bih0  (M=1024, N=1536)
    convertB_kernel<<<(3 * HVAL * 512 + 255) / 256, 256>>>(Wih, 3 * HVAL);
    convertA_kernel<<<(1024 * 512 + 255) / 256, 256>>>(nullptr, 1, TVAL * BVAL);
    bgemm_kernel<<<dim3((TVAL * BVAL) / 128, (3 * HVAL) / 128), 256>>>(
        bih, nullptr, TVAL * BVAL, 3 * HVAL, 2);

    // split Ws now (g_Bsplit free after gx0 gemm); overlaps with recurrence
    convertB_kernel<<<(VVAL * 512 + 255) / 256, 256>>>(Ws, VVAL);

    // recurrence
    for (int t = 0; t < TVAL; t++) {
        int bin = t & 1, bout = (t + 1) & 1;
        gru_step_kernel<false><<<128, 128>>>(nullptr, Whh, nullptr, bhh, t, 0, bin, bout);
        gru_step_kernel<true><<<128, 128>>>(Wih + 3 * HVAL * EVAL, Whh + 3 * HVAL * HVAL,
                                            bih + 3 * HVAL, bhh + 3 * HVAL, t, 1, bin, bout);
        attn_kernel<<<BVAL, 128>>>(enc, mask, bout);
        concat_kernel<<<128, 128>>>(Wc, bc, t, bout);
    }

    // decoder_outputs = concats @ Ws^T + bs  (M=1024, N=50257)
    convertA_kernel<<<(1024 * 512 + 255) / 256, 256>>>(nullptr, 2, TVAL * BVAL);
    bgemm_kernel<<<dim3((TVAL * BVAL) / 128, (VVAL + 127) / 128), 256>>>(
        bs, out, TVAL * BVAL, VVAL, 0);

    // h_final tail
    long main_elems = (long)TVAL * BVAL * VVAL;
    if ((long)out_size >= main_elems + (long)LVAL * BVAL * HVAL)
        final_h_kernel<<<128, 256>>>(out + main_elems);
}